// round 1
// baseline (speedup 1.0000x reference)
#include <cuda_runtime.h>

// Problem constants (fixed by the reference).
#define Bv 2
#define Cv 48
#define Hv 80
#define Wv 128
#define MDv 4
#define RANGEv 81          // (2*MD+1)^2
#define HWv (Hv * Wv)      // 10240
#define CHWv (Cv * HWv)    // 491520

// Normalized-feature scratch (CHW layout, per batch). ~3.75 MB each.
__device__ float g_n1[Bv * CHWv];
__device__ float g_n2[Bv * CHWv];

// ---------------------------------------------------------------------------
// Kernel 1: channel-wise L2 normalization of both features.
// One thread per (b, h, w) pixel; loops channels with stride HW (coalesced
// across the warp at every channel).
// ---------------------------------------------------------------------------
__global__ void normalize_kernel(const float* __restrict__ f1,
                                 const float* __restrict__ f2) {
    int p = blockIdx.x * blockDim.x + threadIdx.x;
    if (p >= Bv * HWv) return;
    int b = p / HWv;
    int hw = p - b * HWv;
    const float* s1 = f1 + b * CHWv + hw;
    const float* s2 = f2 + b * CHWv + hw;
    float* d1 = g_n1 + b * CHWv + hw;
    float* d2 = g_n2 + b * CHWv + hw;

    float sum1 = 0.f, sum2 = 0.f;
#pragma unroll
    for (int c = 0; c < Cv; c++) {
        float v1 = s1[c * HWv];
        float v2 = s2[c * HWv];
        sum1 = fmaf(v1, v1, sum1);
        sum2 = fmaf(v2, v2, sum2);
    }
    float r1 = rsqrtf(sum1 + 1e-6f);
    float r2 = rsqrtf(sum2 + 1e-6f);
#pragma unroll
    for (int c = 0; c < Cv; c++) {
        d1[c * HWv] = s1[c * HWv] * r1;
        d2[c * HWv] = s2[c * HWv] * r2;
    }
}

// ---------------------------------------------------------------------------
// Per-axis sampling helper, replicating the reference exactly:
//   g  = 2*v/(D-1) - 1
//   ix = ((g+1)*D - 1) * 0.5
// Feature path: border clamp (clip ix to [0, D-1], then floor + lerp weight).
// Mask path: unclamped floor, in-bounds indicators, bilinear weight component.
// ---------------------------------------------------------------------------
__device__ __forceinline__ void axis_sample(float v, int D,
                                            int& i0, int& i1, float& wf,
                                            float& mv) {
    float g = (2.0f * v) / (float)(D - 1) - 1.0f;
    float ix = ((g + 1.0f) * (float)D - 1.0f) * 0.5f;

    // feature (border padding)
    float ixb = fminf(fmaxf(ix, 0.0f), (float)(D - 1));
    float x0f = floorf(ixb);
    wf = ixb - x0f;
    i0 = (int)x0f;
    i1 = min(i0 + 1, D - 1);

    // mask (zeros padding indicator)
    float fx = floorf(ix);
    float mw = ix - fx;
    float in0 = (fx >= 0.0f && fx <= (float)(D - 1)) ? 1.0f : 0.0f;
    float in1 = (fx + 1.0f >= 0.0f && fx + 1.0f <= (float)(D - 1)) ? 1.0f : 0.0f;
    mv = (1.0f - mw) * in0 + mw * in1;
}

// ---------------------------------------------------------------------------
// Kernel 2: cost volume.
// Block: (32 w, 9 dv). Thread loops over the 9 du values (x offsets).
// y-axis sampling (depends only on dv) is hoisted out of the du loop.
// t = 0.5 exactly => forward disp = +d, backward disp = -d.
// ---------------------------------------------------------------------------
__global__ __launch_bounds__(288)
void costvol_kernel(const float* __restrict__ BM, float* __restrict__ out) {
    const int w = (blockIdx.x << 5) + threadIdx.x;
    const int dvi = threadIdx.y;           // 0..8  (dv = dvi - 4)
    const int h = blockIdx.y;
    const int b = blockIdx.z;

    const float bmx = BM[((b * 2 + 0) * Hv + h) * Wv + w];
    const float bmy = BM[((b * 2 + 1) * Hv + h) * Wv + w];
    const float dytot = bmy + (float)(dvi - MDv);

    // y sampling: fw uses +dytot, bw uses -dytot. Independent of du.
    int y0f, y1f, y0b, y1b;
    float wyf, wyb, mvyf, mvyb;
    axis_sample((float)h + dytot, Hv, y0f, y1f, wyf, mvyf);
    axis_sample((float)h - dytot, Hv, y0b, y1b, wyb, mvyb);

    const float* __restrict__ p2 = g_n2 + b * CHWv;  // forward-warped source
    const float* __restrict__ p1 = g_n1 + b * CHWv;  // backward-warped source

    const int rowf0 = y0f * Wv, rowf1 = y1f * Wv;
    const int rowb0 = y0b * Wv, rowb1 = y1b * Wv;

    const int obase = ((b * RANGEv + dvi * 9) * Hv + h) * Wv + w;

#pragma unroll
    for (int dui = 0; dui < 9; dui++) {
        const float dxtot = bmx + (float)(dui - MDv);

        int x0f, x1f, x0b, x1b;
        float wxf, wxb, mvxf, mvxb;
        axis_sample((float)w + dxtot, Wv, x0f, x1f, wxf, mvxf);
        axis_sample((float)w - dxtot, Wv, x0b, x1b, wxb, mvxb);

        const float maskf = (mvxf * mvyf < 0.999f) ? 0.0f : 1.0f;
        const float maskb = (mvxb * mvyb < 0.999f) ? 0.0f : 1.0f;

        float acc = 0.0f;
        if (maskf * maskb != 0.0f) {
            // bilinear weights
            const float f00 = (1.0f - wxf) * (1.0f - wyf);
            const float f01 = wxf * (1.0f - wyf);
            const float f10 = (1.0f - wxf) * wyf;
            const float f11 = wxf * wyf;
            const float b00 = (1.0f - wxb) * (1.0f - wyb);
            const float b01 = wxb * (1.0f - wyb);
            const float b10 = (1.0f - wxb) * wyb;
            const float b11 = wxb * wyb;

            const float* q00 = p2 + rowf0 + x0f;
            const float* q01 = p2 + rowf0 + x1f;
            const float* q10 = p2 + rowf1 + x0f;
            const float* q11 = p2 + rowf1 + x1f;
            const float* r00 = p1 + rowb0 + x0b;
            const float* r01 = p1 + rowb0 + x1b;
            const float* r10 = p1 + rowb1 + x0b;
            const float* r11 = p1 + rowb1 + x1b;

#pragma unroll 4
            for (int c = 0; c < Cv; c++) {
                const int o = c * HWv;
                float fw = f00 * q00[o] + f01 * q01[o] + f10 * q10[o] + f11 * q11[o];
                float bw = b00 * r00[o] + b01 * r01[o] + b10 * r10[o] + b11 * r11[o];
                acc = fmaf(fw, bw, acc);
            }
        }
        out[obase + dui * HWv * RANGEv / RANGEv * 0 + dui * Hv * Wv] = acc;
    }
}

// ---------------------------------------------------------------------------
extern "C" void kernel_launch(void* const* d_in, const int* in_sizes, int n_in,
                              void* d_out, int out_size) {
    // metadata order: feature1, feature2, BM — but locate BM by size for safety.
    int bm_idx = 2;
    for (int i = 0; i < n_in; i++)
        if (in_sizes[i] == Bv * 2 * Hv * Wv) bm_idx = i;
    int fidx[2], k = 0;
    for (int i = 0; i < n_in && k < 2; i++)
        if (i != bm_idx) fidx[k++] = i;

    const float* f1 = (const float*)d_in[fidx[0]];
    const float* f2 = (const float*)d_in[fidx[1]];
    const float* BM = (const float*)d_in[bm_idx];
    float* out = (float*)d_out;

    normalize_kernel<<<(Bv * HWv + 255) / 256, 256>>>(f1, f2);

    dim3 grid(Wv / 32, Hv, Bv);
    dim3 blk(32, 9);
    costvol_kernel<<<grid, blk>>>(BM, out);
}

// round 2
// speedup vs baseline: 1.9347x; 1.9347x over previous
#include <cuda_runtime.h>
#include <cuda_fp16.h>

// Problem constants (fixed by the reference).
#define Bv 2
#define Cv 48
#define Hv 80
#define Wv 128
#define MDv 4
#define RANGEv 81          // (2*MD+1)^2
#define HWv (Hv * Wv)      // 10240
#define CHWv (Cv * HWv)    // 491520

// Per-pixel inverse L2 norms.
__device__ float g_rn1[Bv * HWv];
__device__ float g_rn2[Bv * HWv];

// Quad-packed normalized features (fp16). Entry (b,c,y,x) holds the 2x2 tap
// footprint with border replication:
//   .x = half2( v[y ][x], v[y ][x1] )
//   .y = half2( v[y1][x], v[y1][x1] )   where x1=min(x+1,W-1), y1=min(y+1,H-1)
__device__ uint2 g_q1[Bv * CHWv];   // normalized feature1 (backward-warp source)
__device__ uint2 g_q2[Bv * CHWv];   // normalized feature2 (forward-warp source)

// ---------------------------------------------------------------------------
// Kernel 1: per-pixel inverse norms of both features.
// ---------------------------------------------------------------------------
__global__ void rnorm_kernel(const float* __restrict__ f1,
                             const float* __restrict__ f2) {
    int p = blockIdx.x * blockDim.x + threadIdx.x;
    if (p >= Bv * HWv) return;
    int b = p / HWv;
    int hw = p - b * HWv;
    const float* s1 = f1 + b * CHWv + hw;
    const float* s2 = f2 + b * CHWv + hw;
    float sum1 = 0.f, sum2 = 0.f;
#pragma unroll
    for (int c = 0; c < Cv; c++) {
        float v1 = s1[c * HWv];
        float v2 = s2[c * HWv];
        sum1 = fmaf(v1, v1, sum1);
        sum2 = fmaf(v2, v2, sum2);
    }
    g_rn1[p] = rsqrtf(sum1 + 1e-6f);
    g_rn2[p] = rsqrtf(sum2 + 1e-6f);
}

// ---------------------------------------------------------------------------
// Kernel 2: build quad-packed fp16 normalized features.
// One thread per (b,c,y,x); handles both tensors.
// ---------------------------------------------------------------------------
__global__ void pack_kernel(const float* __restrict__ f1,
                            const float* __restrict__ f2) {
    int n = blockIdx.x * blockDim.x + threadIdx.x;
    if (n >= Bv * CHWv) return;
    int x = n & (Wv - 1);
    int t = n >> 7;            // (b*C + c)*H + y
    int y = t % Hv;
    int bc = t / Hv;           // b*C + c
    int b = bc / Cv;

    int x1 = min(x + 1, Wv - 1);
    int y1 = min(y + 1, Hv - 1);

    int rbase = b * HWv;
    float rn1_00 = g_rn1[rbase + y * Wv + x];
    float rn1_01 = g_rn1[rbase + y * Wv + x1];
    float rn1_10 = g_rn1[rbase + y1 * Wv + x];
    float rn1_11 = g_rn1[rbase + y1 * Wv + x1];
    float rn2_00 = g_rn2[rbase + y * Wv + x];
    float rn2_01 = g_rn2[rbase + y * Wv + x1];
    float rn2_10 = g_rn2[rbase + y1 * Wv + x];
    float rn2_11 = g_rn2[rbase + y1 * Wv + x1];

    int cbase = bc * HWv;      // (b*C+c)*HW
    float a00 = f1[cbase + y * Wv + x]   * rn1_00;
    float a01 = f1[cbase + y * Wv + x1]  * rn1_01;
    float a10 = f1[cbase + y1 * Wv + x]  * rn1_10;
    float a11 = f1[cbase + y1 * Wv + x1] * rn1_11;
    float b00 = f2[cbase + y * Wv + x]   * rn2_00;
    float b01 = f2[cbase + y * Wv + x1]  * rn2_01;
    float b10 = f2[cbase + y1 * Wv + x]  * rn2_10;
    float b11 = f2[cbase + y1 * Wv + x1] * rn2_11;

    uint2 q1, q2;
    *reinterpret_cast<half2*>(&q1.x) = __floats2half2_rn(a00, a01);
    *reinterpret_cast<half2*>(&q1.y) = __floats2half2_rn(a10, a11);
    *reinterpret_cast<half2*>(&q2.x) = __floats2half2_rn(b00, b01);
    *reinterpret_cast<half2*>(&q2.y) = __floats2half2_rn(b10, b11);
    g_q1[n] = q1;
    g_q2[n] = q2;
}

// ---------------------------------------------------------------------------
// Per-axis sampling, replicating the reference exactly:
//   g  = 2*v/(D-1) - 1 ; ix = ((g+1)*D - 1) * 0.5
// Feature path: border clamp -> i0 (quad packing bakes i1 replication).
// Mask path: unclamped floor + in-bounds indicators.
// ---------------------------------------------------------------------------
__device__ __forceinline__ void axis_sample(float v, int D,
                                            int& i0, float& wf, float& mv) {
    float g = (2.0f * v) / (float)(D - 1) - 1.0f;
    float ix = ((g + 1.0f) * (float)D - 1.0f) * 0.5f;

    float ixb = fminf(fmaxf(ix, 0.0f), (float)(D - 1));
    float x0f = floorf(ixb);
    wf = ixb - x0f;
    i0 = (int)x0f;

    float fx = floorf(ix);
    float mw = ix - fx;
    float in0 = (fx >= 0.0f && fx <= (float)(D - 1)) ? 1.0f : 0.0f;
    float in1 = (fx + 1.0f >= 0.0f && fx + 1.0f <= (float)(D - 1)) ? 1.0f : 0.0f;
    mv = (1.0f - mw) * in0 + mw * in1;
}

// ---------------------------------------------------------------------------
// Kernel 3: cost volume. Block (32 w, 9 dv); thread loops 9 du.
// t = 0.5 => forward disp = +d (samples f2), backward = -d (samples f1).
// ---------------------------------------------------------------------------
__global__ __launch_bounds__(288)
void costvol_kernel(const float* __restrict__ BM, float* __restrict__ out) {
    const int w = (blockIdx.x << 5) + threadIdx.x;
    const int dvi = threadIdx.y;           // 0..8
    const int h = blockIdx.y;
    const int b = blockIdx.z;

    const float bmx = BM[((b * 2 + 0) * Hv + h) * Wv + w];
    const float bmy = BM[((b * 2 + 1) * Hv + h) * Wv + w];
    const float dytot = bmy + (float)(dvi - MDv);

    int y0f, y0b;
    float wyf, wyb, mvyf, mvyb;
    axis_sample((float)h + dytot, Hv, y0f, wyf, mvyf);
    axis_sample((float)h - dytot, Hv, y0b, wyb, mvyb);

    const uint2* __restrict__ pf = g_q2 + b * CHWv + y0f * Wv;  // forward src
    const uint2* __restrict__ pb = g_q1 + b * CHWv + y0b * Wv;  // backward src

    const float omwyf = 1.0f - wyf;
    const float omwyb = 1.0f - wyb;

    const int obase = ((b * RANGEv + dvi * 9) * Hv + h) * Wv + w;

#pragma unroll
    for (int dui = 0; dui < 9; dui++) {
        const float dxtot = bmx + (float)(dui - MDv);

        int x0f, x0b;
        float wxf, wxb, mvxf, mvxb;
        axis_sample((float)w + dxtot, Wv, x0f, wxf, mvxf);
        axis_sample((float)w - dxtot, Wv, x0b, wxb, mvxb);

        const float maskf = (mvxf * mvyf < 0.999f) ? 0.0f : 1.0f;
        const float maskb = (mvxb * mvyb < 0.999f) ? 0.0f : 1.0f;

        float acc = 0.0f;
        if (maskf * maskb != 0.0f) {
            const float f00 = (1.0f - wxf) * omwyf;
            const float f01 = wxf * omwyf;
            const float f10 = (1.0f - wxf) * wyf;
            const float f11 = wxf * wyf;
            const float g00 = (1.0f - wxb) * omwyb;
            const float g01 = wxb * omwyb;
            const float g10 = (1.0f - wxb) * wyb;
            const float g11 = wxb * wyb;

            const uint2* qf = pf + x0f;
            const uint2* qb = pb + x0b;

#pragma unroll 6
            for (int c = 0; c < Cv; c++) {
                const uint2 uf = qf[c * HWv];
                const uint2 ub = qb[c * HWv];
                const float2 ft = __half22float2(*reinterpret_cast<const half2*>(&uf.x));
                const float2 fb = __half22float2(*reinterpret_cast<const half2*>(&uf.y));
                const float2 bt = __half22float2(*reinterpret_cast<const half2*>(&ub.x));
                const float2 bb = __half22float2(*reinterpret_cast<const half2*>(&ub.y));

                float fw = f00 * ft.x;
                fw = fmaf(f01, ft.y, fw);
                fw = fmaf(f10, fb.x, fw);
                fw = fmaf(f11, fb.y, fw);
                float bw = g00 * bt.x;
                bw = fmaf(g01, bt.y, bw);
                bw = fmaf(g10, bb.x, bw);
                bw = fmaf(g11, bb.y, bw);
                acc = fmaf(fw, bw, acc);
            }
        }
        out[obase + dui * Hv * Wv] = acc;
    }
}

// ---------------------------------------------------------------------------
extern "C" void kernel_launch(void* const* d_in, const int* in_sizes, int n_in,
                              void* d_out, int out_size) {
    int bm_idx = 2;
    for (int i = 0; i < n_in; i++)
        if (in_sizes[i] == Bv * 2 * Hv * Wv) bm_idx = i;
    int fidx[2], k = 0;
    for (int i = 0; i < n_in && k < 2; i++)
        if (i != bm_idx) fidx[k++] = i;

    const float* f1 = (const float*)d_in[fidx[0]];
    const float* f2 = (const float*)d_in[fidx[1]];
    const float* BM = (const float*)d_in[bm_idx];
    float* out = (float*)d_out;

    rnorm_kernel<<<(Bv * HWv + 255) / 256, 256>>>(f1, f2);
    pack_kernel<<<(Bv * CHWv + 255) / 256, 256>>>(f1, f2);

    dim3 grid(Wv / 32, Hv, Bv);
    dim3 blk(32, 9);
    costvol_kernel<<<grid, blk>>>(BM, out);
}